// round 15
// baseline (speedup 1.0000x reference)
#include <cuda_runtime.h>
#include <cuda_fp16.h>
#include <math.h>
#include <stdint.h>

#define BB 2
#define SS 2048
#define DD 2048
#define NH 32
#define NKV 8
#define HD 64
#define RATIO 4
#define MROWS (BB * SS)   // 4096

// ===================== helpers =====================
__device__ __forceinline__ uint32_t smem_u32(const void* p) {
    uint32_t a;
    asm("{ .reg .u64 t; cvta.to.shared.u64 t, %1; cvt.u32.u64 %0, t; }"
        : "=r"(a) : "l"(p));
    return a;
}
__device__ __forceinline__ void cp16(uint32_t dst, const void* src) {
    asm volatile("cp.async.cg.shared.global [%0], [%1], 16;" :: "r"(dst), "l"(src));
}
#define CP_COMMIT() asm volatile("cp.async.commit_group;" ::: "memory")
#define CP_WAIT1()  asm volatile("cp.async.wait_group 1;" ::: "memory")
#define CP_WAIT0()  asm volatile("cp.async.wait_group 0;" ::: "memory")

__device__ __forceinline__ void ldm_x4(uint32_t* r, uint32_t addr) {
    asm volatile("ldmatrix.sync.aligned.m8n8.x4.shared.b16 {%0,%1,%2,%3}, [%4];"
                 : "=r"(r[0]), "=r"(r[1]), "=r"(r[2]), "=r"(r[3]) : "r"(addr));
}
__device__ __forceinline__ void ldm_x4_t(uint32_t* r, uint32_t addr) {
    asm volatile("ldmatrix.sync.aligned.m8n8.x4.trans.shared.b16 {%0,%1,%2,%3}, [%4];"
                 : "=r"(r[0]), "=r"(r[1]), "=r"(r[2]), "=r"(r[3]) : "r"(addr));
}
// fp16 x fp16 -> fp32 MMA
__device__ __forceinline__ void mma_f16(float* d, const uint32_t* a, const uint32_t* b) {
    asm volatile("mma.sync.aligned.m16n8k16.row.col.f32.f16.f16.f32 "
                 "{%0,%1,%2,%3}, {%4,%5,%6,%7}, {%8,%9}, {%0,%1,%2,%3};"
                 : "+f"(d[0]), "+f"(d[1]), "+f"(d[2]), "+f"(d[3])
                 : "r"(a[0]), "r"(a[1]), "r"(a[2]), "r"(a[3]), "r"(b[0]), "r"(b[1]));
}
__device__ __forceinline__ uint32_t pack2h(float lo, float hi) {
    uint32_t r;
    asm("cvt.rn.f16x2.f32 %0, %1, %2;" : "=r"(r) : "f"(hi), "f"(lo));
    return r;
}
__device__ __forceinline__ void split2h(float a, float b, uint32_t& h2, uint32_t& l2) {
    float ah = __half2float(__float2half_rn(a));
    float bh = __half2float(__float2half_rn(b));
    h2 = pack2h(a, b);
    l2 = pack2h(a - ah, b - bh);
}
// fast 2^z for z <= 0 (logits pre-scaled by 1/ln2): FFMA/ALU only
__device__ __forceinline__ float fexp2(float z) {
    z = fmaxf(z, -126.0f);
    float t = z + 12582912.0f;
    int   n = __float_as_int(t) - 0x4B400000;
    float f = z - (t - 12582912.0f);
    float p = 1.540353e-4f;
    p = fmaf(p, f, 1.3333558e-3f);
    p = fmaf(p, f, 9.6181291e-3f);
    p = fmaf(p, f, 5.5504109e-2f);
    p = fmaf(p, f, 2.4022651e-1f);
    p = fmaf(p, f, 6.9314718e-1f);
    p = fmaf(p, f, 1.0f);
    return __int_as_float(__float_as_int(p) + (n << 23));
}

// ===================== scratch =====================
__device__ __half g_xhi[(size_t)MROWS * DD];
__device__ __half g_xlo[(size_t)MROWS * DD];
__device__ __half g_wqh[(size_t)(NH * HD) * DD];
__device__ __half g_wkh[(size_t)(NKV * HD) * DD];
__device__ __half g_wvh[(size_t)(NKV * HD) * DD];
__device__ __half g_woh[(size_t)DD * (NH * HD)];
__device__ __half g_qh[(size_t)BB * NH * SS * HD];
__device__ __half g_ql[(size_t)BB * NH * SS * HD];
__device__ __half g_kh[(size_t)BB * NKV * SS * HD];
__device__ __half g_vh[(size_t)BB * NKV * SS * HD];
__device__ __half g_ohi[(size_t)MROWS * (NH * HD)];
__device__ __half g_olo[(size_t)MROWS * (NH * HD)];

// ===================== fused conversion kernel =====================
__device__ __forceinline__ void do_transpose_h(
    const float* __restrict__ W, __half* __restrict__ Th,
    int K, int N, int n0, int k0, float (*t)[33], int tx, int ty)
{
    #pragma unroll
    for (int i = 0; i < 4; i++)
        t[ty + i * 8][tx] = W[(size_t)(k0 + ty + i * 8) * N + n0 + tx];
    __syncthreads();
    #pragma unroll
    for (int i = 0; i < 4; i++) {
        float f = t[tx][ty + i * 8];
        Th[(size_t)(n0 + ty + i * 8) * K + k0 + tx] = __float2half_rn(f);
    }
}

__global__ void __launch_bounds__(256)
convert_all(const float* __restrict__ x,
            __half* __restrict__ xhi, __half* __restrict__ xlo,
            const float* __restrict__ wq, __half* __restrict__ wqh,
            const float* __restrict__ wk, __half* __restrict__ wkh,
            const float* __restrict__ wv, __half* __restrict__ wvh,
            const float* __restrict__ wo, __half* __restrict__ woh)
{
    __shared__ float t[32][33];
    const int bid = blockIdx.x;
    const int tid = threadIdx.x;

    if (bid < 8192) {
        int i = bid * 256 + tid;
        float4 f = ((const float4*)x)[i];
        uint32_t h2a, l2a, h2b, l2b;
        split2h(f.x, f.y, h2a, l2a);
        split2h(f.z, f.w, h2b, l2b);
        uint2 hh; hh.x = h2a; hh.y = h2b;
        uint2 ll; ll.x = l2a; ll.y = l2b;
        ((uint2*)xhi)[i] = hh;
        ((uint2*)xlo)[i] = ll;
        return;
    }
    const int tx = tid & 31, ty = tid >> 5;
    if (bid < 12288) {
        int local = bid - 8192;
        do_transpose_h(wq, wqh, 2048, 2048, (local & 63) * 32, (local >> 6) * 32, t, tx, ty);
    } else if (bid < 13312) {
        int local = bid - 12288;
        do_transpose_h(wk, wkh, 2048, 512, (local & 15) * 32, (local >> 4) * 32, t, tx, ty);
    } else if (bid < 14336) {
        int local = bid - 13312;
        do_transpose_h(wv, wvh, 2048, 512, (local & 15) * 32, (local >> 4) * 32, t, tx, ty);
    } else {
        int local = bid - 14336;
        do_transpose_h(wo, woh, 2048, 2048, (local & 63) * 32, (local >> 6) * 32, t, tx, ty);
    }
}

// ===================== GEMM config (2-stage, 2 CTAs/SM, 2-pass fp16, BK=64) =====================
#define BMg 128
#define BNg 128
#define BKg 64
#define GK 2048
#define NCH (GK / BKg)                // 32
#define GPITCH 144                    // bytes per row (64 fp16 + 8 pad)
#define TILE_B (128 * GPITCH)         // 18432
#define STAGE_B (3 * TILE_B)          // Ah, Al, Bh = 55296
#define SMEM_GEMM (2 * STAGE_B)       // 110592 (>= Cs 128*132*4 = 67584)
#define CPITCH 132

// Fused QKV projection. grid (32, 24): y<16 Q, 16..19 K, 20..23 V.
__global__ void __launch_bounds__(256, 2)
qkv_gemm(const __half* __restrict__ Ah, const __half* __restrict__ Al,
         const __half* __restrict__ wqh_, const __half* __restrict__ wkh_,
         const __half* __restrict__ wvh_,
         __half* __restrict__ qh_, __half* __restrict__ ql_,
         __half* __restrict__ kh_, __half* __restrict__ vh_,
         const float* __restrict__ q_scale, const float* __restrict__ k_scale,
         const float* __restrict__ cosp, const float* __restrict__ sinp)
{
    extern __shared__ __align__(1024) char smp[];
    const uint32_t smb = smem_u32(smp);
    const int tid = threadIdx.x;
    const int lane = tid & 31, wid = tid >> 5;
    const int wm = wid >> 1, wn = wid & 1;
    const int m0 = wm * 32, n0 = wn * 64;

    const int y = blockIdx.y;
    const __half *Bh;
    __half *outh, *outl;
    const float* scale;
    float qsc;
    int nheads, hbase, rope, osplit;
    size_t brow;
    if (y < 16) {
        Bh = wqh_; outh = qh_; outl = ql_;
        scale = q_scale; qsc = 0.18033688011112042f;   // 0.125 / ln2
        nheads = NH; hbase = y * 2; rope = 1; osplit = 1;
        brow = (size_t)y * BNg;
    } else if (y < 20) {
        Bh = wkh_; outh = kh_; outl = nullptr;
        scale = k_scale; qsc = 1.0f; nheads = NKV; hbase = (y - 16) * 2; rope = 1; osplit = 0;
        brow = (size_t)(y - 16) * BNg;
    } else {
        Bh = wvh_; outh = vh_; outl = nullptr;
        scale = nullptr; qsc = 1.0f; nheads = NKV; hbase = (y - 20) * 2; rope = 0; osplit = 0;
        brow = (size_t)(y - 20) * BNg;
    }

    const size_t arow = (size_t)blockIdx.x * BMg;
    const int lrow = tid >> 1;            // 2 threads per row
    const int lc0 = (tid & 1) * 4;        // 4 x 16B chunks each

    auto load_stage = [&](int ch, int p) {
        const int k0 = ch * BKg;
        uint32_t base = smb + p * STAGE_B;
        size_t ga = (arow + lrow) * GK + k0 + lc0 * 8;
        size_t gb = (brow + lrow) * GK + k0 + lc0 * 8;
        uint32_t soff = lrow * GPITCH + lc0 * 16;
        #pragma unroll
        for (int j = 0; j < 4; j++) {
            cp16(base + soff + j * 16,              Ah + ga + j * 8);
            cp16(base + TILE_B + soff + j * 16,     Al + ga + j * 8);
            cp16(base + 2 * TILE_B + soff + j * 16, Bh + gb + j * 8);
        }
    };

    float c[2][8][4];
    #pragma unroll
    for (int i = 0; i < 2; i++)
        #pragma unroll
        for (int j = 0; j < 8; j++)
            #pragma unroll
            for (int e = 0; e < 4; e++) c[i][j][e] = 0.0f;

    load_stage(0, 0);
    CP_COMMIT();

    const uint32_t a_ro = (uint32_t)(m0 + (lane & 15)) * GPITCH + ((lane >> 4) << 4);
    const uint32_t b_ro = (uint32_t)(n0 + (lane & 7) + ((lane >> 4) << 3)) * GPITCH
                        + (((lane >> 3) & 1) << 4);

    for (int ch = 0; ch < NCH; ch++) {
        const int p = ch & 1;
        if (ch + 1 < NCH) load_stage(ch + 1, p ^ 1);
        CP_COMMIT();
        CP_WAIT1();
        __syncthreads();

        const uint32_t base = smb + p * STAGE_B;
        #pragma unroll
        for (int ks = 0; ks < 4; ks++) {
            uint32_t ah[2][4], al[2][4];
            #pragma unroll
            for (int mt = 0; mt < 2; mt++) {
                uint32_t ad = base + a_ro + mt * 16 * GPITCH + ks * 32;
                ldm_x4(ah[mt], ad);
                ldm_x4(al[mt], ad + TILE_B);
            }
            uint32_t bh[4][4];
            #pragma unroll
            for (int np = 0; np < 4; np++) {
                uint32_t bd = base + 2 * TILE_B + b_ro + np * 16 * GPITCH + ks * 32;
                ldm_x4(bh[np], bd);
            }
            #pragma unroll
            for (int mt = 0; mt < 2; mt++)
                #pragma unroll
                for (int nt = 0; nt < 8; nt++)
                    mma_f16(c[mt][nt], ah[mt], &bh[nt >> 1][(nt & 1) * 2]);
            #pragma unroll
            for (int mt = 0; mt < 2; mt++)
                #pragma unroll
                for (int nt = 0; nt < 8; nt++)
                    mma_f16(c[mt][nt], al[mt], &bh[nt >> 1][(nt & 1) * 2]);
        }
        __syncthreads();
    }

    // ---------------- epilogue ----------------
    float* Cs = (float*)smp;
    const int crow = lane >> 2, ccol = (lane & 3) * 2;
    #pragma unroll
    for (int mt = 0; mt < 2; mt++)
        #pragma unroll
        for (int nt = 0; nt < 8; nt++) {
            int r = m0 + mt * 16 + crow;
            int cc = n0 + nt * 8 + ccol;
            *(float2*)&Cs[r * CPITCH + cc]       = make_float2(c[mt][nt][0], c[mt][nt][1]);
            *(float2*)&Cs[(r + 8) * CPITCH + cc] = make_float2(c[mt][nt][2], c[mt][nt][3]);
        }
    __syncthreads();

    if (rope) {
        const int r = tid & 127, hc = tid >> 7;
        float d[64];
        #pragma unroll
        for (int cc2 = 0; cc2 < 64; cc2++) d[cc2] = Cs[r * CPITCH + hc * 64 + cc2];
        float ssum = 0.0f;
        #pragma unroll
        for (int cc2 = 0; cc2 < 64; cc2++) ssum += d[cc2] * d[cc2];
        float inv = rsqrtf(ssum * (1.0f / 64.0f) + 1e-6f);
        int mglob = blockIdx.x * BMg + r;
        int s = mglob & (SS - 1);
        const float* cr = cosp + (size_t)s * 64;
        const float* sr = sinp + (size_t)s * 64;
        float outv[64];
        #pragma unroll
        for (int cc2 = 0; cc2 < 32; cc2++) {
            float a1 = d[cc2]      * inv * scale[cc2];
            float a2 = d[cc2 + 32] * inv * scale[cc2 + 32];
            outv[cc2]      = (a1 * cr[cc2]      - a2 * sr[cc2])      * qsc;
            outv[cc2 + 32] = (a2 * cr[cc2 + 32] + a1 * sr[cc2 + 32]) * qsc;
        }
        __syncthreads();
        #pragma unroll
        for (int cc2 = 0; cc2 < 64; cc2++) Cs[r * CPITCH + hc * 64 + cc2] = outv[cc2];
        __syncthreads();
    }

    #pragma unroll
    for (int l = 0; l < 16; l++) {
        int gi = tid + l * 256;
        int r = gi >> 5, c4 = gi & 31;
        int col = c4 * 4;
        float4 v = *(float4*)&Cs[r * CPITCH + col];
        int mglob = blockIdx.x * BMg + r;
        int b = mglob >> 11, s = mglob & (SS - 1);
        int hg = hbase + (col >> 6);
        size_t oaddr = (((size_t)b * nheads + hg) * SS + s) * 64 + (col & 63);
        if (osplit) {
            uint32_t h2a, l2a, h2b, l2b;
            split2h(v.x, v.y, h2a, l2a);
            split2h(v.z, v.w, h2b, l2b);
            uint2 hh; hh.x = h2a; hh.y = h2b;
            uint2 ll; ll.x = l2a; ll.y = l2b;
            *(uint2*)(outh + oaddr) = hh;
            *(uint2*)(outl + oaddr) = ll;
        } else {
            uint2 hh; hh.x = pack2h(v.x, v.y); hh.y = pack2h(v.z, v.w);
            *(uint2*)(outh + oaddr) = hh;
        }
    }
}

// Output projection: A split fp16 (2-pass), B single fp16, fp32 out.
__global__ void __launch_bounds__(256, 2)
gemm_out(const __half* __restrict__ Ah, const __half* __restrict__ Al,
         const __half* __restrict__ Bh, float* __restrict__ out)
{
    extern __shared__ __align__(1024) char smp[];
    const uint32_t smb = smem_u32(smp);
    const int tid = threadIdx.x;
    const int lane = tid & 31, wid = tid >> 5;
    const int wm = wid >> 1, wn = wid & 1;
    const int m0 = wm * 32, n0 = wn * 64;

    const size_t arow = (size_t)blockIdx.x * BMg;
    const size_t brow = (size_t)blockIdx.y * BNg;
    const int lrow = tid >> 1;
    const int lc0 = (tid & 1) * 4;

    auto load_stage = [&](int ch, int p) {
        const int k0 = ch * BKg;
        uint32_t base = smb + p * STAGE_B;
        size_t ga = (arow + lrow) * GK + k0 + lc0 * 8;
        size_t gb = (brow + lrow) * GK + k0 + lc0 * 8;
        uint32_t soff = lrow * GPITCH + lc0 * 16;
        #pragma unroll
        for (int j = 0; j < 4; j++) {
            cp16(base + soff + j * 16,              Ah + ga + j * 8);
            cp16(base + TILE_B + soff + j * 16,     Al + ga + j * 8);
            cp16(base + 2 * TILE_B + soff + j * 16, Bh + gb + j * 8);
        }
    };

    float c[2][8][4];
    #pragma unroll
    for (int i = 0; i < 2; i++)
        #pragma unroll
        for (int j = 0; j < 8; j++)
            #pragma unroll
            for (int e = 0; e < 4; e++) c[i][j][e] = 0.0f;

    load_stage(0, 0);
    CP_COMMIT();

    const uint32_t a_ro = (uint32_t)(m0 + (lane & 15)) * GPITCH + ((lane >> 4) << 4);
    const uint32_t b_ro = (uint32_t)(n0 + (lane & 7) + ((lane >> 4) << 3)) * GPITCH
                        + (((lane >> 3) & 1) << 4);

    for (int ch = 0; ch < NCH; ch++) {
        const int p = ch & 1;
        if (ch + 1 < NCH) load_stage(ch + 1, p ^ 1);
        CP_COMMIT();
        CP_WAIT1();
        __syncthreads();

        const uint32_t base = smb + p * STAGE_B;
        #pragma unroll
        for (int ks = 0; ks < 4; ks++) {
            uint32_t ah[2][4], al[2][4];
            #pragma unroll
            for (int mt = 0; mt < 2; mt++) {
                uint32_t ad = base + a_ro + mt * 16 * GPITCH + ks * 32;
                ldm_x4(ah[mt], ad);
                ldm_x4(al[mt], ad + TILE_B);
            }
            uint32_t bh[4][4];
            #pragma unroll
            for (int np = 0; np < 4; np++) {
                uint32_t bd = base + 2 * TILE_B + b_ro + np * 16 * GPITCH + ks * 32;
                ldm_x4(bh[np], bd);
            }
            #pragma unroll
            for (int mt = 0; mt < 2; mt++)
                #pragma unroll
                for (int nt = 0; nt < 8; nt++)
                    mma_f16(c[mt][nt], ah[mt], &bh[nt >> 1][(nt & 1) * 2]);
            #pragma unroll
            for (int mt = 0; mt < 2; mt++)
                #pragma unroll
                for (int nt = 0; nt < 8; nt++)
                    mma_f16(c[mt][nt], al[mt], &bh[nt >> 1][(nt & 1) * 2]);
        }
        __syncthreads();
    }

    float* Cs = (float*)smp;
    const int crow = lane >> 2, ccol = (lane & 3) * 2;
    #pragma unroll
    for (int mt = 0; mt < 2; mt++)
        #pragma unroll
        for (int nt = 0; nt < 8; nt++) {
            int r = m0 + mt * 16 + crow;
            int cc = n0 + nt * 8 + ccol;
            *(float2*)&Cs[r * CPITCH + cc]       = make_float2(c[mt][nt][0], c[mt][nt][1]);
            *(float2*)&Cs[(r + 8) * CPITCH + cc] = make_float2(c[mt][nt][2], c[mt][nt][3]);
        }
    __syncthreads();

    #pragma unroll
    for (int l = 0; l < 16; l++) {
        int gi = tid + l * 256;
        int r = gi >> 5, c4 = gi & 31;
        int col = c4 * 4;
        float4 v = *(float4*)&Cs[r * CPITCH + col];
        int mglob = blockIdx.x * BMg + r;
        size_t oaddr = (size_t)mglob * 2048 + (size_t)blockIdx.y * BNg + col;
        *(float4*)(out + oaddr) = v;
    }
}

// ===================== flash attention (fp16: Q split, K/V single) =====================
#define KV_T2 18432                 // one 128x72 fp16 tensor (pitch 144B)
#define KV_SET 36864                // kh + vh per set
#define SMEM_ATT (2 * KV_SET)       // 73728

__global__ void __launch_bounds__(256, 1)
attn_mma(const __half* __restrict__ qh_g, const __half* __restrict__ ql_g,
         const __half* __restrict__ kh_g, const __half* __restrict__ vh_g,
         __half* __restrict__ oh_g, __half* __restrict__ ol_g)
{
    extern __shared__ __align__(1024) char smp[];
    const uint32_t smb = smem_u32(smp);
    const int tid = threadIdx.x, lane = tid & 31, wid = tid >> 5;
    const int qb = (int)gridDim.x - 1 - (int)blockIdx.x;   // long tiles first
    const int bh = blockIdx.y;
    const int b = bh >> 5, h = bh & 31, hk = h >> 2;
    const int m0 = wid * 16;
    const int nkb = qb + 1;

    const size_t qbase  = (((size_t)b * NH + h) * SS + (size_t)qb * 128) * 64;
    const size_t kvbase = ((size_t)b * NKV + hk) * SS * 64;

    auto load_kv = [&](int kb) {
        const uint32_t base = smb + ((kb & 1) ? KV_SET : 0u);
        const size_t rowb = kvbase + (size_t)kb * 128 * 64;
        #pragma unroll
        for (int i = 0; i < 8; i++) {
            int idx = tid + i * 256;
            int t = idx >> 10, rem = idx & 1023;
            int r = rem >> 3, cc = rem & 7;
            const __half* src = (t == 0) ? kh_g : vh_g;
            cp16(base + t * KV_T2 + r * 144 + cc * 16,
                 src + rowb + (size_t)r * 64 + cc * 8);
        }
    };

    // prologue: Q (hi+lo) -> set1 region, KV0 -> set0
    #pragma unroll
    for (int i = 0; i < 8; i++) {
        int idx = tid + i * 256;
        int t = idx >> 10, rem = idx & 1023;
        int r = rem >> 3, cc = rem & 7;
        const __half* src = (t == 0 ? qh_g : ql_g);
        cp16(smb + KV_SET + t * KV_T2 + r * 144 + cc * 16,
             src + qbase + (size_t)r * 64 + cc * 8);
    }
    load_kv(0);
    CP_COMMIT();
    CP_WAIT0();
    __syncthreads();

    uint32_t qh[4][4], ql[4][4];
    #pragma unroll
    for (int kc = 0; kc < 4; kc++) {
        uint32_t ad = smb + KV_SET + (uint32_t)(m0 + (lane & 15)) * 144
                    + (uint32_t)(kc * 16 + ((lane >> 4) << 3)) * 2;
        ldm_x4(qh[kc], ad);
        ldm_x4(ql[kc], ad + KV_T2);
    }
    __syncthreads();   // Q region free (becomes set1)

    float o[8][4];
    #pragma unroll
    for (int j = 0; j < 8; j++)
        #pragma unroll
        for (int e = 0; e < 4; e++) o[j][e] = 0.0f;
    float rm0 = -1e30f, rm1 = -1e30f, rl0 = 0.0f, rl1 = 0.0f;

    for (int kb = 0; kb < nkb; kb++) {
        if (kb + 1 < nkb) {
            load_kv(kb + 1);
            CP_COMMIT();
            CP_WAIT1();
        } else {
            CP_WAIT0();
        }
        __syncthreads();
        const uint32_t setb = smb + ((kb & 1) ? KV_SET : 0u);

        // ---- S = Q K^T (Q split, K single) ----
        float sc[16][4];
        #pragma unroll
        for (int j = 0; j < 16; j++)
            #pragma unroll
            for (int e = 0; e < 4; e++) sc[j][e] = 0.0f;

        #pragma unroll
        for (int kc = 0; kc < 4; kc++) {
            #pragma unroll
            for (int g = 0; g < 8; g++) {
                uint32_t ad = setb
                    + (uint32_t)(g * 16 + (lane & 7) + ((lane >> 4) << 3)) * 144
                    + (uint32_t)(kc * 16 + (((lane >> 3) & 1) << 3)) * 2;
                uint32_t kh4[4];
                ldm_x4(kh4, ad);
                mma_f16(sc[2 * g],     qh[kc], &kh4[0]);
                mma_f16(sc[2 * g + 1], qh[kc], &kh4[2]);
                mma_f16(sc[2 * g],     ql[kc], &kh4[0]);
                mma_f16(sc[2 * g + 1], ql[kc], &kh4[2]);
            }
        }

        // ---- causal mask (diagonal 128x128 block) ----
        if (kb == qb) {
            int row0 = qb * 128 + m0 + (lane >> 2);
            int col0 = kb * 128 + (lane & 3) * 2;
            #pragma unroll
            for (int nt = 0; nt < 16; nt++) {
                int cl = col0 + nt * 8;
                if (cl     > row0)     sc[nt][0] = -1e30f;
                if (cl + 1 > row0)     sc[nt][1] = -1e30f;
                if (cl     > row0 + 8) sc[nt][2] = -1e30f;
                if (cl + 1 > row0 + 8) sc[nt][3] = -1e30f;
            }
        }

        // ---- online softmax (base-2) ----
        float mx0 = -1e30f, mx1 = -1e30f;
        #pragma unroll
        for (int nt = 0; nt < 16; nt++) {
            mx0 = fmaxf(mx0, fmaxf(sc[nt][0], sc[nt][1]));
            mx1 = fmaxf(mx1, fmaxf(sc[nt][2], sc[nt][3]));
        }
        mx0 = fmaxf(mx0, __shfl_xor_sync(0xffffffffu, mx0, 1));
        mx0 = fmaxf(mx0, __shfl_xor_sync(0xffffffffu, mx0, 2));
        mx1 = fmaxf(mx1, __shfl_xor_sync(0xffffffffu, mx1, 1));
        mx1 = fmaxf(mx1, __shfl_xor_sync(0xffffffffu, mx1, 2));
        float nm0 = fmaxf(rm0, mx0), nm1 = fmaxf(rm1, mx1);
        float a0 = fexp2(rm0 - nm0), a1 = fexp2(rm1 - nm1);
        rm0 = nm0; rm1 = nm1;
        float ps0 = 0.0f, ps1 = 0.0f;
        #pragma unroll
        for (int nt = 0; nt < 16; nt++) {
            sc[nt][0] = fexp2(sc[nt][0] - rm0); ps0 += sc[nt][0];
            sc[nt][1] = fexp2(sc[nt][1] - rm0); ps0 += sc[nt][1];
            sc[nt][2] = fexp2(sc[nt][2] - rm1); ps1 += sc[nt][2];
            sc[nt][3] = fexp2(sc[nt][3] - rm1); ps1 += sc[nt][3];
        }
        #pragma unroll
        for (int nt = 0; nt < 8; nt++) {
            o[nt][0] *= a0; o[nt][1] *= a0; o[nt][2] *= a1; o[nt][3] *= a1;
        }
        rl0 = rl0 * a0 + ps0;
        rl1 = rl1 * a1 + ps1;

        // ---- O += P V (P split, V single) ----
        #pragma unroll
        for (int s = 0; s < 8; s++) {
            uint32_t ah[4], al[4];
            split2h(sc[2 * s][0],     sc[2 * s][1],     ah[0], al[0]);
            split2h(sc[2 * s][2],     sc[2 * s][3],     ah[1], al[1]);
            split2h(sc[2 * s + 1][0], sc[2 * s + 1][1], ah[2], al[2]);
            split2h(sc[2 * s + 1][2], sc[2 * s + 1][3], ah[3], al[3]);
            #pragma unroll
            for (int g = 0; g < 4; g++) {
                uint32_t ad = setb + KV_T2        // Vh
                    + (uint32_t)(s * 16 + (lane & 7) + (((lane >> 3) & 1) << 3)) * 144
                    + (uint32_t)(g * 16 + ((lane >> 4) << 3)) * 2;
                uint32_t vh4[4];
                ldm_x4_t(vh4, ad);
                mma_f16(o[2 * g],     ah, &vh4[0]);
                mma_f16(o[2 * g + 1], ah, &vh4[2]);
                mma_f16(o[2 * g],     al, &vh4[0]);
                mma_f16(o[2 * g + 1], al, &vh4[2]);
            }
        }
        __syncthreads();
    }

    // ---- finalize, stage O in set0 region, coalesced writeout ----
    rl0 += __shfl_xor_sync(0xffffffffu, rl0, 1);
    rl0 += __shfl_xor_sync(0xffffffffu, rl0, 2);
    rl1 += __shfl_xor_sync(0xffffffffu, rl1, 1);
    rl1 += __shfl_xor_sync(0xffffffffu, rl1, 2);
    float inv0 = 1.0f / rl0, inv1 = 1.0f / rl1;

    __syncthreads();
    #pragma unroll
    for (int nt = 0; nt < 8; nt++) {
        uint32_t off0 = (uint32_t)(m0 + (lane >> 2)) * 144 + (uint32_t)(nt * 8 + (lane & 3) * 2) * 2;
        uint32_t off1 = off0 + 8 * 144;
        uint32_t h2, l2;
        split2h(o[nt][0] * inv0, o[nt][1] * inv0, h2, l2);
        *(uint32_t*)(smp + off0)         = h2;
        *(uint32_t*)(smp + KV_T2 + off0) = l2;
        split2h(o[nt][2] * inv1, o[nt][3] * inv1, h2, l2);
        *(uint32_t*)(smp + off1)         = h2;
        *(uint32_t*)(smp + KV_T2 + off1) = l2;
    }
    __syncthreads();

    const size_t obase = ((size_t)b * SS + (size_t)qb * 128) * 2048 + (size_t)h * 64;
    #pragma unroll
    for (int i = 0; i < 4; i++) {
        int idx = tid + i * 256;
        int r = idx >> 3, cc = idx & 7;
        uint4 vh = *(uint4*)(smp + r * 144 + cc * 16);
        uint4 vl = *(uint4*)(smp + KV_T2 + r * 144 + cc * 16);
        size_t oa = obase + (size_t)r * 2048 + cc * 8;
        *(uint4*)(oh_g + oa) = vh;
        *(uint4*)(ol_g + oa) = vl;
    }
}

// ===================== launch =====================
extern "C" void kernel_launch(void* const* d_in, const int* in_sizes, int n_in,
                              void* d_out, int out_size)
{
    const float* x       = (const float*)d_in[0];
    const float* wq      = (const float*)d_in[1];
    const float* wk      = (const float*)d_in[2];
    const float* wv      = (const float*)d_in[3];
    const float* wo      = (const float*)d_in[4];
    const float* q_scale = (const float*)d_in[5];
    const float* k_scale = (const float*)d_in[6];
    const float* cosp    = (const float*)d_in[7];
    const float* sinp    = (const float*)d_in[8];

    __half *xhi, *xlo, *wqh, *wkh, *wvh, *woh;
    __half *qh, *ql, *kh, *vh, *ohi, *olo;
    cudaGetSymbolAddress((void**)&xhi, g_xhi); cudaGetSymbolAddress((void**)&xlo, g_xlo);
    cudaGetSymbolAddress((void**)&wqh, g_wqh); cudaGetSymbolAddress((void**)&wkh, g_wkh);
    cudaGetSymbolAddress((void**)&wvh, g_wvh); cudaGetSymbolAddress((void**)&woh, g_woh);
    cudaGetSymbolAddress((void**)&qh, g_qh);   cudaGetSymbolAddress((void**)&ql, g_ql);
    cudaGetSymbolAddress((void**)&kh, g_kh);   cudaGetSymbolAddress((void**)&vh, g_vh);
    cudaGetSymbolAddress((void**)&ohi, g_ohi); cudaGetSymbolAddress((void**)&olo, g_olo);

    cudaFuncSetAttribute(qkv_gemm, cudaFuncAttributeMaxDynamicSharedMemorySize, SMEM_GEMM);
    cudaFuncSetAttribute(gemm_out, cudaFuncAttributeMaxDynamicSharedMemorySize, SMEM_GEMM);
    cudaFuncSetAttribute(attn_mma, cudaFuncAttributeMaxDynamicSharedMemorySize, SMEM_ATT);

    // ---- fused conversions (one launch) ----
    convert_all<<<18432, 256>>>(x, xhi, xlo, wq, wqh, wk, wkh, wv, wvh, wo, woh);

    // ---- fused QKV projection (2-pass fp16, BK=64) ----
    qkv_gemm<<<dim3(MROWS / BMg, 24), 256, SMEM_GEMM>>>(
        xhi, xlo, wqh, wkh, wvh, qh, ql, kh, vh, q_scale, k_scale, cosp, sinp);

    // ---- attention (Q/P split, K/V single fp16) ----
    attn_mma<<<dim3(SS / 128, BB * NH), 256, SMEM_ATT>>>(qh, ql, kh, vh, ohi, olo);

    // ---- output projection (2-pass fp16, BK=64) ----
    gemm_out<<<dim3(MROWS / BMg, DD / BNg), 256, SMEM_GEMM>>>(
        ohi, olo, woh, (float*)d_out);
}

// round 16
// speedup vs baseline: 1.2507x; 1.2507x over previous
#include <cuda_runtime.h>
#include <cuda_fp16.h>
#include <math.h>
#include <stdint.h>

#define BB 2
#define SS 2048
#define DD 2048
#define NH 32
#define NKV 8
#define HD 64
#define RATIO 4
#define MROWS (BB * SS)   // 4096

// ===================== helpers =====================
__device__ __forceinline__ uint32_t smem_u32(const void* p) {
    uint32_t a;
    asm("{ .reg .u64 t; cvta.to.shared.u64 t, %1; cvt.u32.u64 %0, t; }"
        : "=r"(a) : "l"(p));
    return a;
}
__device__ __forceinline__ void cp16(uint32_t dst, const void* src) {
    asm volatile("cp.async.cg.shared.global [%0], [%1], 16;" :: "r"(dst), "l"(src));
}
#define CP_COMMIT() asm volatile("cp.async.commit_group;" ::: "memory")
#define CP_WAIT1()  asm volatile("cp.async.wait_group 1;" ::: "memory")
#define CP_WAIT0()  asm volatile("cp.async.wait_group 0;" ::: "memory")

__device__ __forceinline__ void ldm_x4(uint32_t* r, uint32_t addr) {
    asm volatile("ldmatrix.sync.aligned.m8n8.x4.shared.b16 {%0,%1,%2,%3}, [%4];"
                 : "=r"(r[0]), "=r"(r[1]), "=r"(r[2]), "=r"(r[3]) : "r"(addr));
}
__device__ __forceinline__ void ldm_x4_t(uint32_t* r, uint32_t addr) {
    asm volatile("ldmatrix.sync.aligned.m8n8.x4.trans.shared.b16 {%0,%1,%2,%3}, [%4];"
                 : "=r"(r[0]), "=r"(r[1]), "=r"(r[2]), "=r"(r[3]) : "r"(addr));
}
// fp16 x fp16 -> fp32 MMA
__device__ __forceinline__ void mma_f16(float* d, const uint32_t* a, const uint32_t* b) {
    asm volatile("mma.sync.aligned.m16n8k16.row.col.f32.f16.f16.f32 "
                 "{%0,%1,%2,%3}, {%4,%5,%6,%7}, {%8,%9}, {%0,%1,%2,%3};"
                 : "+f"(d[0]), "+f"(d[1]), "+f"(d[2]), "+f"(d[3])
                 : "r"(a[0]), "r"(a[1]), "r"(a[2]), "r"(a[3]), "r"(b[0]), "r"(b[1]));
}
__device__ __forceinline__ uint32_t pack2h(float lo, float hi) {
    uint32_t r;
    asm("cvt.rn.f16x2.f32 %0, %1, %2;" : "=r"(r) : "f"(hi), "f"(lo));
    return r;
}
__device__ __forceinline__ void split2h(float a, float b, uint32_t& h2, uint32_t& l2) {
    float ah = __half2float(__float2half_rn(a));
    float bh = __half2float(__float2half_rn(b));
    h2 = pack2h(a, b);
    l2 = pack2h(a - ah, b - bh);
}
// fast 2^z for z <= 0 (logits pre-scaled by 1/ln2): FFMA/ALU only
__device__ __forceinline__ float fexp2(float z) {
    z = fmaxf(z, -126.0f);
    float t = z + 12582912.0f;
    int   n = __float_as_int(t) - 0x4B400000;
    float f = z - (t - 12582912.0f);
    float p = 1.540353e-4f;
    p = fmaf(p, f, 1.3333558e-3f);
    p = fmaf(p, f, 9.6181291e-3f);
    p = fmaf(p, f, 5.5504109e-2f);
    p = fmaf(p, f, 2.4022651e-1f);
    p = fmaf(p, f, 6.9314718e-1f);
    p = fmaf(p, f, 1.0f);
    return __int_as_float(__float_as_int(p) + (n << 23));
}

// ===================== scratch =====================
__device__ __half g_xhi[(size_t)MROWS * DD];
__device__ __half g_xlo[(size_t)MROWS * DD];
__device__ __half g_wqh[(size_t)(NH * HD) * DD];
__device__ __half g_wkh[(size_t)(NKV * HD) * DD];
__device__ __half g_wvh[(size_t)(NKV * HD) * DD];
__device__ __half g_woh[(size_t)DD * (NH * HD)];
__device__ __half g_qh[(size_t)BB * NH * SS * HD];
__device__ __half g_ql[(size_t)BB * NH * SS * HD];
__device__ __half g_kh[(size_t)BB * NKV * SS * HD];
__device__ __half g_vh[(size_t)BB * NKV * SS * HD];
__device__ __half g_ohi[(size_t)MROWS * (NH * HD)];

// ===================== fused conversion kernel =====================
__device__ __forceinline__ void do_transpose_h(
    const float* __restrict__ W, __half* __restrict__ Th,
    int K, int N, int n0, int k0, float (*t)[33], int tx, int ty)
{
    #pragma unroll
    for (int i = 0; i < 4; i++)
        t[ty + i * 8][tx] = W[(size_t)(k0 + ty + i * 8) * N + n0 + tx];
    __syncthreads();
    #pragma unroll
    for (int i = 0; i < 4; i++) {
        float f = t[tx][ty + i * 8];
        Th[(size_t)(n0 + ty + i * 8) * K + k0 + tx] = __float2half_rn(f);
    }
}

__global__ void __launch_bounds__(256)
convert_all(const float* __restrict__ x,
            __half* __restrict__ xhi, __half* __restrict__ xlo,
            const float* __restrict__ wq, __half* __restrict__ wqh,
            const float* __restrict__ wk, __half* __restrict__ wkh,
            const float* __restrict__ wv, __half* __restrict__ wvh,
            const float* __restrict__ wo, __half* __restrict__ woh)
{
    __shared__ float t[32][33];
    const int bid = blockIdx.x;
    const int tid = threadIdx.x;

    if (bid < 8192) {
        int i = bid * 256 + tid;
        float4 f = ((const float4*)x)[i];
        uint32_t h2a, l2a, h2b, l2b;
        split2h(f.x, f.y, h2a, l2a);
        split2h(f.z, f.w, h2b, l2b);
        uint2 hh; hh.x = h2a; hh.y = h2b;
        uint2 ll; ll.x = l2a; ll.y = l2b;
        ((uint2*)xhi)[i] = hh;
        ((uint2*)xlo)[i] = ll;
        return;
    }
    const int tx = tid & 31, ty = tid >> 5;
    if (bid < 12288) {
        int local = bid - 8192;
        do_transpose_h(wq, wqh, 2048, 2048, (local & 63) * 32, (local >> 6) * 32, t, tx, ty);
    } else if (bid < 13312) {
        int local = bid - 12288;
        do_transpose_h(wk, wkh, 2048, 512, (local & 15) * 32, (local >> 4) * 32, t, tx, ty);
    } else if (bid < 14336) {
        int local = bid - 13312;
        do_transpose_h(wv, wvh, 2048, 512, (local & 15) * 32, (local >> 4) * 32, t, tx, ty);
    } else {
        int local = bid - 14336;
        do_transpose_h(wo, woh, 2048, 2048, (local & 63) * 32, (local >> 6) * 32, t, tx, ty);
    }
}

// ===================== GEMM config (R14 exact: BK=32, 2-stage, 2 CTAs/SM) =====================
#define BMg 128
#define BNg 128
#define BKg 32
#define GK 2048
#define NCH (GK / BKg)
#define APAD 40
#define TILE_B (128 * APAD * 2)
#define STAGE_B (3 * TILE_B)          // qkv: Ah, Al, Bh = 30720
#define STAGE_B2 (2 * TILE_B)         // gemm_out: Ah, Bh = 20480
#define CPITCH 132
#define SMEM_GEMM (128 * CPITCH * 4)  // 67584 >= 2*STAGE_B (61440) >= 2*STAGE_B2

// Fused QKV projection. grid (32, 24): y<16 Q, 16..19 K, 20..23 V. (R14 exact)
__global__ void __launch_bounds__(256, 2)
qkv_gemm(const __half* __restrict__ Ah, const __half* __restrict__ Al,
         const __half* __restrict__ wqh_, const __half* __restrict__ wkh_,
         const __half* __restrict__ wvh_,
         __half* __restrict__ qh_, __half* __restrict__ ql_,
         __half* __restrict__ kh_, __half* __restrict__ vh_,
         const float* __restrict__ q_scale, const float* __restrict__ k_scale,
         const float* __restrict__ cosp, const float* __restrict__ sinp)
{
    extern __shared__ __align__(1024) char smp[];
    const uint32_t smb = smem_u32(smp);
    const int tid = threadIdx.x;
    const int lane = tid & 31, wid = tid >> 5;
    const int wm = wid >> 1, wn = wid & 1;
    const int m0 = wm * 32, n0 = wn * 64;

    const int y = blockIdx.y;
    const __half *Bh;
    __half *outh, *outl;
    const float* scale;
    float qsc;
    int nheads, hbase, rope, osplit;
    size_t brow;
    if (y < 16) {
        Bh = wqh_; outh = qh_; outl = ql_;
        scale = q_scale; qsc = 0.18033688011112042f;   // 0.125 / ln2
        nheads = NH; hbase = y * 2; rope = 1; osplit = 1;
        brow = (size_t)y * BNg;
    } else if (y < 20) {
        Bh = wkh_; outh = kh_; outl = nullptr;
        scale = k_scale; qsc = 1.0f; nheads = NKV; hbase = (y - 16) * 2; rope = 1; osplit = 0;
        brow = (size_t)(y - 16) * BNg;
    } else {
        Bh = wvh_; outh = vh_; outl = nullptr;
        scale = nullptr; qsc = 1.0f; nheads = NKV; hbase = (y - 20) * 2; rope = 0; osplit = 0;
        brow = (size_t)(y - 20) * BNg;
    }

    const size_t arow = (size_t)blockIdx.x * BMg;
    const int lrow = tid >> 1;
    const int lc0 = (tid & 1) * 2;

    auto load_stage = [&](int ch, int p) {
        const int k0 = ch * BKg;
        uint32_t base = smb + p * STAGE_B;
        size_t ga = (arow + lrow) * GK + k0 + lc0 * 8;
        size_t gb = (brow + lrow) * GK + k0 + lc0 * 8;
        uint32_t soff = lrow * (APAD * 2) + lc0 * 16;
        #pragma unroll
        for (int j = 0; j < 2; j++) {
            cp16(base + soff + j * 16,              Ah + ga + j * 8);
            cp16(base + TILE_B + soff + j * 16,     Al + ga + j * 8);
            cp16(base + 2 * TILE_B + soff + j * 16, Bh + gb + j * 8);
        }
    };

    float c[2][8][4];
    #pragma unroll
    for (int i = 0; i < 2; i++)
        #pragma unroll
        for (int j = 0; j < 8; j++)
            #pragma unroll
            for (int e = 0; e < 4; e++) c[i][j][e] = 0.0f;

    load_stage(0, 0);
    CP_COMMIT();

    const uint32_t a_ro = (uint32_t)(m0 + (lane & 15)) * (APAD * 2) + ((lane >> 4) << 4);
    const uint32_t b_ro = (uint32_t)(n0 + (lane & 7) + ((lane >> 4) << 3)) * (APAD * 2)
                        + (((lane >> 3) & 1) << 4);

    for (int ch = 0; ch < NCH; ch++) {
        const int p = ch & 1;
        if (ch + 1 < NCH) load_stage(ch + 1, p ^ 1);
        CP_COMMIT();
        CP_WAIT1();
        __syncthreads();

        const uint32_t base = smb + p * STAGE_B;
        #pragma unroll
        for (int ks = 0; ks < 2; ks++) {
            uint32_t ah[2][4], al[2][4];
            #pragma unroll
            for (int mt = 0; mt < 2; mt++) {
                uint32_t ad = base + a_ro + mt * 16 * (APAD * 2) + ks * 32;
                ldm_x4(ah[mt], ad);
                ldm_x4(al[mt], ad + TILE_B);
            }
            uint32_t bh[4][4];
            #pragma unroll
            for (int np = 0; np < 4; np++) {
                uint32_t bd = base + 2 * TILE_B + b_ro + np * 16 * (APAD * 2) + ks * 32;
                ldm_x4(bh[np], bd);
            }
            #pragma unroll
            for (int mt = 0; mt < 2; mt++)
                #pragma unroll
                for (int nt = 0; nt < 8; nt++)
                    mma_f16(c[mt][nt], ah[mt], &bh[nt >> 1][(nt & 1) * 2]);
            #pragma unroll
            for (int mt = 0; mt < 2; mt++)
                #pragma unroll
                for (int nt = 0; nt < 8; nt++)
                    mma_f16(c[mt][nt], al[mt], &bh[nt >> 1][(nt & 1) * 2]);
        }
        __syncthreads();
    }

    // ---------------- epilogue ----------------
    float* Cs = (float*)smp;
    const int crow = lane >> 2, ccol = (lane & 3) * 2;
    #pragma unroll
    for (int mt = 0; mt < 2; mt++)
        #pragma unroll
        for (int nt = 0; nt < 8; nt++) {
            int r = m0 + mt * 16 + crow;
            int cc = n0 + nt * 8 + ccol;
            *(float2*)&Cs[r * CPITCH + cc]       = make_float2(c[mt][nt][0], c[mt][nt][1]);
            *(float2*)&Cs[(r + 8) * CPITCH + cc] = make_float2(c[mt][nt][2], c[mt][nt][3]);
        }
    __syncthreads();

    if (rope) {
        const int r = tid & 127, hc = tid >> 7;
        float d[64];
        #pragma unroll
        for (int cc2 = 0; cc2 < 64; cc2++) d[cc2] = Cs[r * CPITCH + hc * 64 + cc2];
        float ssum = 0.0f;
        #pragma unroll
        for (int cc2 = 0; cc2 < 64; cc2++) ssum += d[cc2] * d[cc2];
        float inv = rsqrtf(ssum * (1.0f / 64.0f) + 1e-6f);
        int mglob = blockIdx.x * BMg + r;
        int s = mglob & (SS - 1);
        const float* cr = cosp + (size_t)s * 64;
        const float* sr = sinp + (size_t)s * 64;
        float outv[64];
        #pragma unroll
        for (int cc2 = 0; cc2 < 32; cc2++) {
            float a1 = d[cc2]      * inv * scale[cc2];
            float a2 = d[cc2 + 32] * inv * scale[cc2 + 32];
            outv[cc2]      = (a1 * cr[cc2]      - a2 * sr[cc2])      * qsc;
            outv[cc2 + 32] = (a2 * cr[cc2 + 32] + a1 * sr[cc2 + 32]) * qsc;
        }
        __syncthreads();
        #pragma unroll
        for (int cc2 = 0; cc2 < 64; cc2++) Cs[r * CPITCH + hc * 64 + cc2] = outv[cc2];
        __syncthreads();
    }

    #pragma unroll
    for (int l = 0; l < 16; l++) {
        int gi = tid + l * 256;
        int r = gi >> 5, c4 = gi & 31;
        int col = c4 * 4;
        float4 v = *(float4*)&Cs[r * CPITCH + col];
        int mglob = blockIdx.x * BMg + r;
        int b = mglob >> 11, s = mglob & (SS - 1);
        int hg = hbase + (col >> 6);
        size_t oaddr = (((size_t)b * nheads + hg) * SS + s) * 64 + (col & 63);
        if (osplit) {
            uint32_t h2a, l2a, h2b, l2b;
            split2h(v.x, v.y, h2a, l2a);
            split2h(v.z, v.w, h2b, l2b);
            uint2 hh; hh.x = h2a; hh.y = h2b;
            uint2 ll; ll.x = l2a; ll.y = l2b;
            *(uint2*)(outh + oaddr) = hh;
            *(uint2*)(outl + oaddr) = ll;
        } else {
            uint2 hh; hh.x = pack2h(v.x, v.y); hh.y = pack2h(v.z, v.w);
            *(uint2*)(outh + oaddr) = hh;
        }
    }
}

// Output projection: single-pass fp16 (A = attention O, fp16 unsplit), fp32 out.
__global__ void __launch_bounds__(256, 2)
gemm_out(const __half* __restrict__ Ah, const __half* __restrict__ Bh,
         float* __restrict__ out)
{
    extern __shared__ __align__(1024) char smp[];
    const uint32_t smb = smem_u32(smp);
    const int tid = threadIdx.x;
    const int lane = tid & 31, wid = tid >> 5;
    const int wm = wid >> 1, wn = wid & 1;
    const int m0 = wm * 32, n0 = wn * 64;

    const size_t arow = (size_t)blockIdx.x * BMg;
    const size_t brow = (size_t)blockIdx.y * BNg;
    const int lrow = tid >> 1;
    const int lc0 = (tid & 1) * 2;

    auto load_stage = [&](int ch, int p) {
        const int k0 = ch * BKg;
        uint32_t base = smb + p * STAGE_B2;
        size_t ga = (arow + lrow) * GK + k0 + lc0 * 8;
        size_t gb = (brow + lrow) * GK + k0 + lc0 * 8;
        uint32_t soff = lrow * (APAD * 2) + lc0 * 16;
        #pragma unroll
        for (int j = 0; j < 2; j++) {
            cp16(base + soff + j * 16,          Ah + ga + j * 8);
            cp16(base + TILE_B + soff + j * 16, Bh + gb + j * 8);
        }
    };

    float c[2][8][4];
    #pragma unroll
    for (int i = 0; i < 2; i++)
        #pragma unroll
        for (int j = 0; j < 8; j++)
            #pragma unroll
            for (int e = 0; e < 4; e++) c[i][j][e] = 0.0f;

    load_stage(0, 0);
    CP_COMMIT();

    const uint32_t a_ro = (uint32_t)(m0 + (lane & 15)) * (APAD * 2) + ((lane >> 4) << 4);
    const uint32_t b_ro = (uint32_t)(n0 + (lane & 7) + ((lane >> 4) << 3)) * (APAD * 2)
                        + (((lane >> 3) & 1) << 4);

    for (int ch = 0; ch < NCH; ch++) {
        const int p = ch & 1;
        if (ch + 1 < NCH) load_stage(ch + 1, p ^ 1);
        CP_COMMIT();
        CP_WAIT1();
        __syncthreads();

        const uint32_t base = smb + p * STAGE_B2;
        #pragma unroll
        for (int ks = 0; ks < 2; ks++) {
            uint32_t ah[2][4];
            #pragma unroll
            for (int mt = 0; mt < 2; mt++) {
                uint32_t ad = base + a_ro + mt * 16 * (APAD * 2) + ks * 32;
                ldm_x4(ah[mt], ad);
            }
            uint32_t bh[4][4];
            #pragma unroll
            for (int np = 0; np < 4; np++) {
                uint32_t bd = base + TILE_B + b_ro + np * 16 * (APAD * 2) + ks * 32;
                ldm_x4(bh[np], bd);
            }
            #pragma unroll
            for (int mt = 0; mt < 2; mt++)
                #pragma unroll
                for (int nt = 0; nt < 8; nt++)
                    mma_f16(c[mt][nt], ah[mt], &bh[nt >> 1][(nt & 1) * 2]);
        }
        __syncthreads();
    }

    float* Cs = (float*)smp;
    const int crow = lane >> 2, ccol = (lane & 3) * 2;
    #pragma unroll
    for (int mt = 0; mt < 2; mt++)
        #pragma unroll
        for (int nt = 0; nt < 8; nt++) {
            int r = m0 + mt * 16 + crow;
            int cc = n0 + nt * 8 + ccol;
            *(float2*)&Cs[r * CPITCH + cc]       = make_float2(c[mt][nt][0], c[mt][nt][1]);
            *(float2*)&Cs[(r + 8) * CPITCH + cc] = make_float2(c[mt][nt][2], c[mt][nt][3]);
        }
    __syncthreads();

    #pragma unroll
    for (int l = 0; l < 16; l++) {
        int gi = tid + l * 256;
        int r = gi >> 5, c4 = gi & 31;
        int col = c4 * 4;
        float4 v = *(float4*)&Cs[r * CPITCH + col];
        int mglob = blockIdx.x * BMg + r;
        size_t oaddr = (size_t)mglob * 2048 + (size_t)blockIdx.y * BNg + col;
        *(float4*)(out + oaddr) = v;
    }
}

// ===================== flash attention (fp16: Q/P split, K/V single, O unsplit) =====================
#define KV_T2 18432                 // one 128x72 fp16 tensor (pitch 144B)
#define KV_SET 36864                // kh + vh per set
#define SMEM_ATT (2 * KV_SET)       // 73728

__global__ void __launch_bounds__(256, 1)
attn_mma(const __half* __restrict__ qh_g, const __half* __restrict__ ql_g,
         const __half* __restrict__ kh_g, const __half* __restrict__ vh_g,
         __half* __restrict__ oh_g)
{
    extern __shared__ __align__(1024) char smp[];
    const uint32_t smb = smem_u32(smp);
    const int tid = threadIdx.x, lane = tid & 31, wid = tid >> 5;
    const int qb = (int)gridDim.x - 1 - (int)blockIdx.x;   // long tiles first
    const int bh = blockIdx.y;
    const int b = bh >> 5, h = bh & 31, hk = h >> 2;
    const int m0 = wid * 16;
    const int nkb = qb + 1;

    const size_t qbase  = (((size_t)b * NH + h) * SS + (size_t)qb * 128) * 64;
    const size_t kvbase = ((size_t)b * NKV + hk) * SS * 64;

    auto load_kv = [&](int kb) {
        const uint32_t base = smb + ((kb & 1) ? KV_SET : 0u);
        const size_t rowb = kvbase + (size_t)kb * 128 * 64;
        #pragma unroll
        for (int i = 0; i < 8; i++) {
            int idx = tid + i * 256;
            int t = idx >> 10, rem = idx & 1023;
            int r = rem >> 3, cc = rem & 7;
            const __half* src = (t == 0) ? kh_g : vh_g;
            cp16(base + t * KV_T2 + r * 144 + cc * 16,
                 src + rowb + (size_t)r * 64 + cc * 8);
        }
    };

    // prologue: Q (hi+lo) -> set1 region, KV0 -> set0
    #pragma unroll
    for (int i = 0; i < 8; i++) {
        int idx = tid + i * 256;
        int t = idx >> 10, rem = idx & 1023;
        int r = rem >> 3, cc = rem & 7;
        const __half* src = (t == 0 ? qh_g : ql_g);
        cp16(smb + KV_SET + t * KV_T2 + r * 144 + cc * 16,
             src + qbase + (size_t)r * 64 + cc * 8);
    }
    load_kv(0);
    CP_COMMIT();
    CP_WAIT0();
    __syncthreads();

    uint32_t qh[4][4], ql[4][4];
    #pragma unroll
    for (int kc = 0; kc < 4; kc++) {
        uint32_t ad = smb + KV_SET + (uint32_t)(m0 + (lane & 15)) * 144
                    + (uint32_t)(kc * 16 + ((lane >> 4) << 3)) * 2;
        ldm_x4(qh[kc], ad);
        ldm_x4(ql[kc], ad + KV_T2);
    }
    __syncthreads();   // Q region free (becomes set1)

    float o[8][4];
    #pragma unroll
    for (int j = 0; j < 8; j++)
        #pragma unroll
        for (int e = 0; e < 4; e++) o[j][e] = 0.0f;
    float rm0 = -1e30f, rm1 = -1e30f, rl0 = 0.0f, rl1 = 0.0f;

    for (int kb = 0; kb < nkb; kb++) {
        if (kb + 1 < nkb) {
            load_kv(kb + 1);
            CP_COMMIT();
            CP_WAIT1();
        } else {
            CP_WAIT0();
        }
        __syncthreads();
        const uint32_t setb = smb + ((kb & 1) ? KV_SET : 0u);

        // ---- S = Q K^T (Q split, K single) ----
        float sc[16][4];
        #pragma unroll
        for (int j = 0; j < 16; j++)
            #pragma unroll
            for (int e = 0; e < 4; e++) sc[j][e] = 0.0f;

        #pragma unroll
        for (int kc = 0; kc < 4; kc++) {
            #pragma unroll
            for (int g = 0; g < 8; g++) {
                uint32_t ad = setb
                    + (uint32_t)(g * 16 + (lane & 7) + ((lane >> 4) << 3)) * 144
                    + (uint32_t)(kc * 16 + (((lane >> 3) & 1) << 3)) * 2;
                uint32_t kh4[4];
                ldm_x4(kh4, ad);
                mma_f16(sc[2 * g],     qh[kc], &kh4[0]);
                mma_f16(sc[2 * g + 1], qh[kc], &kh4[2]);
                mma_f16(sc[2 * g],     ql[kc], &kh4[0]);
                mma_f16(sc[2 * g + 1], ql[kc], &kh4[2]);
            }
        }

        // ---- causal mask (diagonal 128x128 block) ----
        if (kb == qb) {
            int row0 = qb * 128 + m0 + (lane >> 2);
            int col0 = kb * 128 + (lane & 3) * 2;
            #pragma unroll
            for (int nt = 0; nt < 16; nt++) {
                int cl = col0 + nt * 8;
                if (cl     > row0)     sc[nt][0] = -1e30f;
                if (cl + 1 > row0)     sc[nt][1] = -1e30f;
                if (cl     > row0 + 8) sc[nt][2] = -1e30f;
                if (cl + 1 > row0 + 8) sc[nt][3] = -1e30f;
            }
        }

        // ---- online softmax (base-2) ----
        float mx0 = -1e30f, mx1 = -1e30f;
        #pragma unroll
        for (int nt = 0; nt < 16; nt++) {
            mx0 = fmaxf(mx0, fmaxf(sc[nt][0], sc[nt][1]));
            mx1 = fmaxf(mx1, fmaxf(sc[nt][2], sc[nt][3]));
        }
        mx0 = fmaxf(mx0, __shfl_xor_sync(0xffffffffu, mx0, 1));
        mx0 = fmaxf(mx0, __shfl_xor_sync(0xffffffffu, mx0, 2));
        mx1 = fmaxf(mx1, __shfl_xor_sync(0xffffffffu, mx1, 1));
        mx1 = fmaxf(mx1, __shfl_xor_sync(0xffffffffu, mx1, 2));
        float nm0 = fmaxf(rm0, mx0), nm1 = fmaxf(rm1, mx1);
        float a0 = fexp2(rm0 - nm0), a1 = fexp2(rm1 - nm1);
        rm0 = nm0; rm1 = nm1;
        float ps0 = 0.0f, ps1 = 0.0f;
        #pragma unroll
        for (int nt = 0; nt < 16; nt++) {
            sc[nt][0] = fexp2(sc[nt][0] - rm0); ps0 += sc[nt][0];
            sc[nt][1] = fexp2(sc[nt][1] - rm0); ps0 += sc[nt][1];
            sc[nt][2] = fexp2(sc[nt][2] - rm1); ps1 += sc[nt][2];
            sc[nt][3] = fexp2(sc[nt][3] - rm1); ps1 += sc[nt][3];
        }
        #pragma unroll
        for (int nt = 0; nt < 8; nt++) {
            o[nt][0] *= a0; o[nt][1] *= a0; o[nt][2] *= a1; o[nt][3] *= a1;
        }
        rl0 = rl0 * a0 + ps0;
        rl1 = rl1 * a1 + ps1;

        // ---- O += P V (P split, V single) ----
        #pragma unroll
        for (int s = 0; s < 8; s++) {
            uint32_t ah[4], al[4];
            split2h(sc[2 * s][0],     sc[2 * s][1],     ah[0], al[0]);
            split2h(sc[2 * s][2],     sc[2 * s][3],     ah[1], al[1]);
            split2h(sc[2 * s + 1][0], sc[2 * s + 1][1], ah[2], al[2]);
            split2h(sc[2 * s + 1][2], sc[2 * s + 1][3], ah[3], al[3]);
            #pragma unroll
            for (int g = 0; g < 4; g++) {
                uint32_t ad = setb + KV_T2        // Vh
                    + (uint32_t)(s * 16 + (lane & 7) + (((lane >> 3) & 1) << 3)) * 144
                    + (uint32_t)(g * 16 + ((lane >> 4) << 3)) * 2;
                uint32_t vh4[4];
                ldm_x4_t(vh4, ad);
                mma_f16(o[2 * g],     ah, &vh4[0]);
                mma_f16(o[2 * g + 1], ah, &vh4[2]);
                mma_f16(o[2 * g],     al, &vh4[0]);
                mma_f16(o[2 * g + 1], al, &vh4[2]);
            }
        }
        __syncthreads();
    }

    // ---- finalize, stage O (fp16, unsplit) in set0 region, coalesced writeout ----
    rl0 += __shfl_xor_sync(0xffffffffu, rl0, 1);
    rl0 += __shfl_xor_sync(0xffffffffu, rl0, 2);
    rl1 += __shfl_xor_sync(0xffffffffu, rl1, 1);
    rl1 += __shfl_xor_sync(0xffffffffu, rl1, 2);
    float inv0 = 1.0f / rl0, inv1 = 1.0f / rl1;

    __syncthreads();
    #pragma unroll
    for (int nt = 0; nt < 8; nt++) {
        uint32_t off0 = (uint32_t)(m0 + (lane >> 2)) * 144 + (uint32_t)(nt * 8 + (lane & 3) * 2) * 2;
        uint32_t off1 = off0 + 8 * 144;
        *(uint32_t*)(smp + off0) = pack2h(o[nt][0] * inv0, o[nt][1] * inv0);
        *(uint32_t*)(smp + off1) = pack2h(o[nt][2] * inv1, o[nt][3] * inv1);
    }
    __syncthreads();

    const size_t obase = ((size_t)b * SS + (size_t)qb * 128) * 2048 + (size_t)h * 64;
    #pragma unroll
    for (int i = 0; i < 4; i++) {
        int idx = tid + i * 256;
        int r = idx >> 3, cc = idx & 7;
        uint4 vh = *(uint4*)(smp + r * 144 + cc * 16);
        size_t oa = obase + (size_t)r * 2048 + cc * 8;
        *(uint4*)(oh_g + oa) = vh;
    }
}

// ===================== launch =====================
extern "C" void kernel_launch(void* const* d_in, const int* in_sizes, int n_in,
                              void* d_out, int out_size)
{
    const float* x       = (const float*)d_in[0];
    const float* wq      = (const float*)d_in[1];
    const float* wk      = (const float*)d_in[2];
    const float* wv      = (const float*)d_in[3];
    const float* wo      = (const float*)d_in[4];
    const float* q_scale = (const float*)d_in[5];
    const float* k_scale = (const float*)d_in[6];
    const float* cosp    = (const float*)d_in[7];
    const float* sinp    = (const float*)d_in[8];

    __half *xhi, *xlo, *wqh, *wkh, *wvh, *woh;
    __half *qh, *ql, *kh, *vh, *ohi;
    cudaGetSymbolAddress((void**)&xhi, g_xhi); cudaGetSymbolAddress((void**)&xlo, g_xlo);
    cudaGetSymbolAddress((void**)&wqh, g_wqh); cudaGetSymbolAddress((void**)&wkh, g_wkh);
    cudaGetSymbolAddress((void**)&wvh, g_wvh); cudaGetSymbolAddress((void**)&woh, g_woh);
    cudaGetSymbolAddress((void**)&qh, g_qh);   cudaGetSymbolAddress((void**)&ql, g_ql);
    cudaGetSymbolAddress((void**)&kh, g_kh);   cudaGetSymbolAddress((void**)&vh, g_vh);
    cudaGetSymbolAddress((void**)&ohi, g_ohi);

    cudaFuncSetAttribute(qkv_gemm, cudaFuncAttributeMaxDynamicSharedMemorySize, SMEM_GEMM);
    cudaFuncSetAttribute(gemm_out, cudaFuncAttributeMaxDynamicSharedMemorySize, SMEM_GEMM);
    cudaFuncSetAttribute(attn_mma, cudaFuncAttributeMaxDynamicSharedMemorySize, SMEM_ATT);

    // ---- fused conversions (one launch) ----
    convert_all<<<18432, 256>>>(x, xhi, xlo, wq, wqh, wk, wkh, wv, wvh, wo, woh);

    // ---- fused QKV projection (2-pass fp16, BK=32) ----
    qkv_gemm<<<dim3(MROWS / BMg, 24), 256, SMEM_GEMM>>>(
        xhi, xlo, wqh, wkh, wvh, qh, ql, kh, vh, q_scale, k_scale, cosp, sinp);

    // ---- attention (Q/P split, K/V single fp16, O unsplit) ----
    attn_mma<<<dim3(SS / 128, BB * NH), 256, SMEM_ATT>>>(qh, ql, kh, vh, ohi);

    // ---- output projection (single-pass fp16) ----
    gemm_out<<<dim3(MROWS / BMg, DD / BNg), 256, SMEM_GEMM>>>(
        ohi, woh, (float*)d_out);
}

// round 17
// speedup vs baseline: 1.4678x; 1.1735x over previous
#include <cuda_runtime.h>
#include <cuda_fp16.h>
#include <math.h>
#include <stdint.h>

#define BB 2
#define SS 2048
#define DD 2048
#define NH 32
#define NKV 8
#define HD 64
#define RATIO 4
#define MROWS (BB * SS)   // 4096

// ===================== helpers =====================
__device__ __forceinline__ uint32_t smem_u32(const void* p) {
    uint32_t a;
    asm("{ .reg .u64 t; cvta.to.shared.u64 t, %1; cvt.u32.u64 %0, t; }"
        : "=r"(a) : "l"(p));
    return a;
}
__device__ __forceinline__ void cp16(uint32_t dst, const void* src) {
    asm volatile("cp.async.cg.shared.global [%0], [%1], 16;" :: "r"(dst), "l"(src));
}
#define CP_COMMIT() asm volatile("cp.async.commit_group;" ::: "memory")
#define CP_WAIT1()  asm volatile("cp.async.wait_group 1;" ::: "memory")
#define CP_WAIT0()  asm volatile("cp.async.wait_group 0;" ::: "memory")

__device__ __forceinline__ void ldm_x4(uint32_t* r, uint32_t addr) {
    asm volatile("ldmatrix.sync.aligned.m8n8.x4.shared.b16 {%0,%1,%2,%3}, [%4];"
                 : "=r"(r[0]), "=r"(r[1]), "=r"(r[2]), "=r"(r[3]) : "r"(addr));
}
__device__ __forceinline__ void ldm_x4_t(uint32_t* r, uint32_t addr) {
    asm volatile("ldmatrix.sync.aligned.m8n8.x4.trans.shared.b16 {%0,%1,%2,%3}, [%4];"
                 : "=r"(r[0]), "=r"(r[1]), "=r"(r[2]), "=r"(r[3]) : "r"(addr));
}
// fp16 x fp16 -> fp32 MMA
__device__ __forceinline__ void mma_f16(float* d, const uint32_t* a, const uint32_t* b) {
    asm volatile("mma.sync.aligned.m16n8k16.row.col.f32.f16.f16.f32 "
                 "{%0,%1,%2,%3}, {%4,%5,%6,%7}, {%8,%9}, {%0,%1,%2,%3};"
                 : "+f"(d[0]), "+f"(d[1]), "+f"(d[2]), "+f"(d[3])
                 : "r"(a[0]), "r"(a[1]), "r"(a[2]), "r"(a[3]), "r"(b[0]), "r"(b[1]));
}
__device__ __forceinline__ uint32_t pack2h(float lo, float hi) {
    uint32_t r;
    asm("cvt.rn.f16x2.f32 %0, %1, %2;" : "=r"(r) : "f"(hi), "f"(lo));
    return r;
}
__device__ __forceinline__ void split2h(float a, float b, uint32_t& h2, uint32_t& l2) {
    float ah = __half2float(__float2half_rn(a));
    float bh = __half2float(__float2half_rn(b));
    h2 = pack2h(a, b);
    l2 = pack2h(a - ah, b - bh);
}
// fast 2^z for z <= 0 (logits pre-scaled by 1/ln2): FFMA/ALU only
__device__ __forceinline__ float fexp2(float z) {
    z = fmaxf(z, -126.0f);
    float t = z + 12582912.0f;
    int   n = __float_as_int(t) - 0x4B400000;
    float f = z - (t - 12582912.0f);
    float p = 1.540353e-4f;
    p = fmaf(p, f, 1.3333558e-3f);
    p = fmaf(p, f, 9.6181291e-3f);
    p = fmaf(p, f, 5.5504109e-2f);
    p = fmaf(p, f, 2.4022651e-1f);
    p = fmaf(p, f, 6.9314718e-1f);
    p = fmaf(p, f, 1.0f);
    return __int_as_float(__float_as_int(p) + (n << 23));
}

// ===================== scratch =====================
__device__ __half g_xhi[(size_t)MROWS * DD];
__device__ __half g_wqh[(size_t)(NH * HD) * DD];
__device__ __half g_wkh[(size_t)(NKV * HD) * DD];
__device__ __half g_wvh[(size_t)(NKV * HD) * DD];
__device__ __half g_woh[(size_t)DD * (NH * HD)];
__device__ __half g_qh[(size_t)BB * NH * SS * HD];
__device__ __half g_ql[(size_t)BB * NH * SS * HD];
__device__ __half g_kh[(size_t)BB * NKV * SS * HD];
__device__ __half g_vh[(size_t)BB * NKV * SS * HD];
__device__ __half g_ohi[(size_t)MROWS * (NH * HD)];

// ===================== fused conversion kernel =====================
__device__ __forceinline__ void do_transpose_h(
    const float* __restrict__ W, __half* __restrict__ Th,
    int K, int N, int n0, int k0, float (*t)[33], int tx, int ty)
{
    #pragma unroll
    for (int i = 0; i < 4; i++)
        t[ty + i * 8][tx] = W[(size_t)(k0 + ty + i * 8) * N + n0 + tx];
    __syncthreads();
    #pragma unroll
    for (int i = 0; i < 4; i++) {
        float f = t[tx][ty + i * 8];
        Th[(size_t)(n0 + ty + i * 8) * K + k0 + tx] = __float2half_rn(f);
    }
}

__global__ void __launch_bounds__(256)
convert_all(const float* __restrict__ x, __half* __restrict__ xhi,
            const float* __restrict__ wq, __half* __restrict__ wqh,
            const float* __restrict__ wk, __half* __restrict__ wkh,
            const float* __restrict__ wv, __half* __restrict__ wvh,
            const float* __restrict__ wo, __half* __restrict__ woh)
{
    __shared__ float t[32][33];
    const int bid = blockIdx.x;
    const int tid = threadIdx.x;

    if (bid < 8192) {
        int i = bid * 256 + tid;
        float4 f = ((const float4*)x)[i];
        uint2 hh;
        hh.x = pack2h(f.x, f.y);
        hh.y = pack2h(f.z, f.w);
        ((uint2*)xhi)[i] = hh;
        return;
    }
    const int tx = tid & 31, ty = tid >> 5;
    if (bid < 12288) {
        int local = bid - 8192;
        do_transpose_h(wq, wqh, 2048, 2048, (local & 63) * 32, (local >> 6) * 32, t, tx, ty);
    } else if (bid < 13312) {
        int local = bid - 12288;
        do_transpose_h(wk, wkh, 2048, 512, (local & 15) * 32, (local >> 4) * 32, t, tx, ty);
    } else if (bid < 14336) {
        int local = bid - 13312;
        do_transpose_h(wv, wvh, 2048, 512, (local & 15) * 32, (local >> 4) * 32, t, tx, ty);
    } else {
        int local = bid - 14336;
        do_transpose_h(wo, woh, 2048, 2048, (local & 63) * 32, (local >> 6) * 32, t, tx, ty);
    }
}

// ===================== GEMM config (BK=32, 2-stage, 2 CTAs/SM, single-pass fp16) =====================
#define BMg 128
#define BNg 128
#define BKg 32
#define GK 2048
#define NCH (GK / BKg)
#define APAD 40
#define TILE_B (128 * APAD * 2)
#define STAGE_B2 (2 * TILE_B)         // Ah, Bh = 20480
#define CPITCH 132
#define SMEM_GEMM (128 * CPITCH * 4)  // 67584 >= 2*STAGE_B2 (40960)

// Fused QKV projection (single-pass fp16). grid (32, 24): y<16 Q, 16..19 K, 20..23 V.
__global__ void __launch_bounds__(256, 2)
qkv_gemm(const __half* __restrict__ Ah,
         const __half* __restrict__ wqh_, const __half* __restrict__ wkh_,
         const __half* __restrict__ wvh_,
         __half* __restrict__ qh_, __half* __restrict__ ql_,
         __half* __restrict__ kh_, __half* __restrict__ vh_,
         const float* __restrict__ q_scale, const float* __restrict__ k_scale,
         const float* __restrict__ cosp, const float* __restrict__ sinp)
{
    extern __shared__ __align__(1024) char smp[];
    const uint32_t smb = smem_u32(smp);
    const int tid = threadIdx.x;
    const int lane = tid & 31, wid = tid >> 5;
    const int wm = wid >> 1, wn = wid & 1;
    const int m0 = wm * 32, n0 = wn * 64;

    const int y = blockIdx.y;
    const __half *Bh;
    __half *outh, *outl;
    const float* scale;
    float qsc;
    int nheads, hbase, rope, osplit;
    size_t brow;
    if (y < 16) {
        Bh = wqh_; outh = qh_; outl = ql_;
        scale = q_scale; qsc = 0.18033688011112042f;   // 0.125 / ln2
        nheads = NH; hbase = y * 2; rope = 1; osplit = 1;
        brow = (size_t)y * BNg;
    } else if (y < 20) {
        Bh = wkh_; outh = kh_; outl = nullptr;
        scale = k_scale; qsc = 1.0f; nheads = NKV; hbase = (y - 16) * 2; rope = 1; osplit = 0;
        brow = (size_t)(y - 16) * BNg;
    } else {
        Bh = wvh_; outh = vh_; outl = nullptr;
        scale = nullptr; qsc = 1.0f; nheads = NKV; hbase = (y - 20) * 2; rope = 0; osplit = 0;
        brow = (size_t)(y - 20) * BNg;
    }

    const size_t arow = (size_t)blockIdx.x * BMg;
    const int lrow = tid >> 1;
    const int lc0 = (tid & 1) * 2;

    auto load_stage = [&](int ch, int p) {
        const int k0 = ch * BKg;
        uint32_t base = smb + p * STAGE_B2;
        size_t ga = (arow + lrow) * GK + k0 + lc0 * 8;
        size_t gb = (brow + lrow) * GK + k0 + lc0 * 8;
        uint32_t soff = lrow * (APAD * 2) + lc0 * 16;
        #pragma unroll
        for (int j = 0; j < 2; j++) {
            cp16(base + soff + j * 16,          Ah + ga + j * 8);
            cp16(base + TILE_B + soff + j * 16, Bh + gb + j * 8);
        }
    };

    float c[2][8][4];
    #pragma unroll
    for (int i = 0; i < 2; i++)
        #pragma unroll
        for (int j = 0; j < 8; j++)
            #pragma unroll
            for (int e = 0; e < 4; e++) c[i][j][e] = 0.0f;

    load_stage(0, 0);
    CP_COMMIT();

    const uint32_t a_ro = (uint32_t)(m0 + (lane & 15)) * (APAD * 2) + ((lane >> 4) << 4);
    const uint32_t b_ro = (uint32_t)(n0 + (lane & 7) + ((lane >> 4) << 3)) * (APAD * 2)
                        + (((lane >> 3) & 1) << 4);

    for (int ch = 0; ch < NCH; ch++) {
        const int p = ch & 1;
        if (ch + 1 < NCH) load_stage(ch + 1, p ^ 1);
        CP_COMMIT();
        CP_WAIT1();
        __syncthreads();

        const uint32_t base = smb + p * STAGE_B2;
        #pragma unroll
        for (int ks = 0; ks < 2; ks++) {
            uint32_t ah[2][4];
            #pragma unroll
            for (int mt = 0; mt < 2; mt++) {
                uint32_t ad = base + a_ro + mt * 16 * (APAD * 2) + ks * 32;
                ldm_x4(ah[mt], ad);
            }
            uint32_t bh[4][4];
            #pragma unroll
            for (int np = 0; np < 4; np++) {
                uint32_t bd = base + TILE_B + b_ro + np * 16 * (APAD * 2) + ks * 32;
                ldm_x4(bh[np], bd);
            }
            #pragma unroll
            for (int mt = 0; mt < 2; mt++)
                #pragma unroll
                for (int nt = 0; nt < 8; nt++)
                    mma_f16(c[mt][nt], ah[mt], &bh[nt >> 1][(nt & 1) * 2]);
        }
        __syncthreads();
    }

    // ---------------- epilogue ----------------
    float* Cs = (float*)smp;
    const int crow = lane >> 2, ccol = (lane & 3) * 2;
    #pragma unroll
    for (int mt = 0; mt < 2; mt++)
        #pragma unroll
        for (int nt = 0; nt < 8; nt++) {
            int r = m0 + mt * 16 + crow;
            int cc = n0 + nt * 8 + ccol;
            *(float2*)&Cs[r * CPITCH + cc]       = make_float2(c[mt][nt][0], c[mt][nt][1]);
            *(float2*)&Cs[(r + 8) * CPITCH + cc] = make_float2(c[mt][nt][2], c[mt][nt][3]);
        }
    __syncthreads();

    if (rope) {
        const int r = tid & 127, hc = tid >> 7;
        float d[64];
        #pragma unroll
        for (int cc2 = 0; cc2 < 64; cc2++) d[cc2] = Cs[r * CPITCH + hc * 64 + cc2];
        float ssum = 0.0f;
        #pragma unroll
        for (int cc2 = 0; cc2 < 64; cc2++) ssum += d[cc2] * d[cc2];
        float inv = rsqrtf(ssum * (1.0f / 64.0f) + 1e-6f);
        int mglob = blockIdx.x * BMg + r;
        int s = mglob & (SS - 1);
        const float* cr = cosp + (size_t)s * 64;
        const float* sr = sinp + (size_t)s * 64;
        float outv[64];
        #pragma unroll
        for (int cc2 = 0; cc2 < 32; cc2++) {
            float a1 = d[cc2]      * inv * scale[cc2];
            float a2 = d[cc2 + 32] * inv * scale[cc2 + 32];
            outv[cc2]      = (a1 * cr[cc2]      - a2 * sr[cc2])      * qsc;
            outv[cc2 + 32] = (a2 * cr[cc2 + 32] + a1 * sr[cc2 + 32]) * qsc;
        }
        __syncthreads();
        #pragma unroll
        for (int cc2 = 0; cc2 < 64; cc2++) Cs[r * CPITCH + hc * 64 + cc2] = outv[cc2];
        __syncthreads();
    }

    #pragma unroll
    for (int l = 0; l < 16; l++) {
        int gi = tid + l * 256;
        int r = gi >> 5, c4 = gi & 31;
        int col = c4 * 4;
        float4 v = *(float4*)&Cs[r * CPITCH + col];
        int mglob = blockIdx.x * BMg + r;
        int b = mglob >> 11, s = mglob & (SS - 1);
        int hg = hbase + (col >> 6);
        size_t oaddr = (((size_t)b * nheads + hg) * SS + s) * 64 + (col & 63);
        if (osplit) {
            uint32_t h2a, l2a, h2b, l2b;
            split2h(v.x, v.y, h2a, l2a);
            split2h(v.z, v.w, h2b, l2b);
            uint2 hh; hh.x = h2a; hh.y = h2b;
            uint2 ll; ll.x = l2a; ll.y = l2b;
            *(uint2*)(outh + oaddr) = hh;
            *(uint2*)(outl + oaddr) = ll;
        } else {
            uint2 hh; hh.x = pack2h(v.x, v.y); hh.y = pack2h(v.z, v.w);
            *(uint2*)(outh + oaddr) = hh;
        }
    }
}

// Output projection: single-pass fp16, fp32 out.
__global__ void __launch_bounds__(256, 2)
gemm_out(const __half* __restrict__ Ah, const __half* __restrict__ Bh,
         float* __restrict__ out)
{
    extern __shared__ __align__(1024) char smp[];
    const uint32_t smb = smem_u32(smp);
    const int tid = threadIdx.x;
    const int lane = tid & 31, wid = tid >> 5;
    const int wm = wid >> 1, wn = wid & 1;
    const int m0 = wm * 32, n0 = wn * 64;

    const size_t arow = (size_t)blockIdx.x * BMg;
    const size_t brow = (size_t)blockIdx.y * BNg;
    const int lrow = tid >> 1;
    const int lc0 = (tid & 1) * 2;

    auto load_stage = [&](int ch, int p) {
        const int k0 = ch * BKg;
        uint32_t base = smb + p * STAGE_B2;
        size_t ga = (arow + lrow) * GK + k0 + lc0 * 8;
        size_t gb = (brow + lrow) * GK + k0 + lc0 * 8;
        uint32_t soff = lrow * (APAD * 2) + lc0 * 16;
        #pragma unroll
        for (int j = 0; j < 2; j++) {
            cp16(base + soff + j * 16,          Ah + ga + j * 8);
            cp16(base + TILE_B + soff + j * 16, Bh + gb + j * 8);
        }
    };

    float c[2][8][4];
    #pragma unroll
    for (int i = 0; i < 2; i++)
        #pragma unroll
        for (int j = 0; j < 8; j++)
            #pragma unroll
            for (int e = 0; e < 4; e++) c[i][j][e] = 0.0f;

    load_stage(0, 0);
    CP_COMMIT();

    const uint32_t a_ro = (uint32_t)(m0 + (lane & 15)) * (APAD * 2) + ((lane >> 4) << 4);
    const uint32_t b_ro = (uint32_t)(n0 + (lane & 7) + ((lane >> 4) << 3)) * (APAD * 2)
                        + (((lane >> 3) & 1) << 4);

    for (int ch = 0; ch < NCH; ch++) {
        const int p = ch & 1;
        if (ch + 1 < NCH) load_stage(ch + 1, p ^ 1);
        CP_COMMIT();
        CP_WAIT1();
        __syncthreads();

        const uint32_t base = smb + p * STAGE_B2;
        #pragma unroll
        for (int ks = 0; ks < 2; ks++) {
            uint32_t ah[2][4];
            #pragma unroll
            for (int mt = 0; mt < 2; mt++) {
                uint32_t ad = base + a_ro + mt * 16 * (APAD * 2) + ks * 32;
                ldm_x4(ah[mt], ad);
            }
            uint32_t bh[4][4];
            #pragma unroll
            for (int np = 0; np < 4; np++) {
                uint32_t bd = base + TILE_B + b_ro + np * 16 * (APAD * 2) + ks * 32;
                ldm_x4(bh[np], bd);
            }
            #pragma unroll
            for (int mt = 0; mt < 2; mt++)
                #pragma unroll
                for (int nt = 0; nt < 8; nt++)
                    mma_f16(c[mt][nt], ah[mt], &bh[nt >> 1][(nt & 1) * 2]);
        }
        __syncthreads();
    }

    float* Cs = (float*)smp;
    const int crow = lane >> 2, ccol = (lane & 3) * 2;
    #pragma unroll
    for (int mt = 0; mt < 2; mt++)
        #pragma unroll
        for (int nt = 0; nt < 8; nt++) {
            int r = m0 + mt * 16 + crow;
            int cc = n0 + nt * 8 + ccol;
            *(float2*)&Cs[r * CPITCH + cc]       = make_float2(c[mt][nt][0], c[mt][nt][1]);
            *(float2*)&Cs[(r + 8) * CPITCH + cc] = make_float2(c[mt][nt][2], c[mt][nt][3]);
        }
    __syncthreads();

    #pragma unroll
    for (int l = 0; l < 16; l++) {
        int gi = tid + l * 256;
        int r = gi >> 5, c4 = gi & 31;
        int col = c4 * 4;
        float4 v = *(float4*)&Cs[r * CPITCH + col];
        int mglob = blockIdx.x * BMg + r;
        size_t oaddr = (size_t)mglob * 2048 + (size_t)blockIdx.y * BNg + col;
        *(float4*)(out + oaddr) = v;
    }
}

// ===================== flash attention (fp16: Q/P split, K/V single, O unsplit) =====================
#define KV_T2 18432                 // one 128x72 fp16 tensor (pitch 144B)
#define KV_SET 36864                // kh + vh per set
#define SMEM_ATT (2 * KV_SET)       // 73728

__global__ void __launch_bounds__(256, 1)
attn_mma(const __half* __restrict__ qh_g, const __half* __restrict__ ql_g,
         const __half* __restrict__ kh_g, const __half* __restrict__ vh_g,
         __half* __restrict__ oh_g)
{
    extern __shared__ __align__(1024) char smp[];
    const uint32_t smb = smem_u32(smp);
    const int tid = threadIdx.x, lane = tid & 31, wid = tid >> 5;
    const int qb = (int)gridDim.x - 1 - (int)blockIdx.x;   // long tiles first
    const int bh = blockIdx.y;
    const int b = bh >> 5, h = bh & 31, hk = h >> 2;
    const int m0 = wid * 16;
    const int nkb = qb + 1;

    const size_t qbase  = (((size_t)b * NH + h) * SS + (size_t)qb * 128) * 64;
    const size_t kvbase = ((size_t)b * NKV + hk) * SS * 64;

    auto load_kv = [&](int kb) {
        const uint32_t base = smb + ((kb & 1) ? KV_SET : 0u);
        const size_t rowb = kvbase + (size_t)kb * 128 * 64;
        #pragma unroll
        for (int i = 0; i < 8; i++) {
            int idx = tid + i * 256;
            int t = idx >> 10, rem = idx & 1023;
            int r = rem >> 3, cc = rem & 7;
            const __half* src = (t == 0) ? kh_g : vh_g;
            cp16(base + t * KV_T2 + r * 144 + cc * 16,
                 src + rowb + (size_t)r * 64 + cc * 8);
        }
    };

    // prologue: Q (hi+lo) -> set1 region, KV0 -> set0
    #pragma unroll
    for (int i = 0; i < 8; i++) {
        int idx = tid + i * 256;
        int t = idx >> 10, rem = idx & 1023;
        int r = rem >> 3, cc = rem & 7;
        const __half* src = (t == 0 ? qh_g : ql_g);
        cp16(smb + KV_SET + t * KV_T2 + r * 144 + cc * 16,
             src + qbase + (size_t)r * 64 + cc * 8);
    }
    load_kv(0);
    CP_COMMIT();
    CP_WAIT0();
    __syncthreads();

    uint32_t qh[4][4], ql[4][4];
    #pragma unroll
    for (int kc = 0; kc < 4; kc++) {
        uint32_t ad = smb + KV_SET + (uint32_t)(m0 + (lane & 15)) * 144
                    + (uint32_t)(kc * 16 + ((lane >> 4) << 3)) * 2;
        ldm_x4(qh[kc], ad);
        ldm_x4(ql[kc], ad + KV_T2);
    }
    __syncthreads();   // Q region free (becomes set1)

    float o[8][4];
    #pragma unroll
    for (int j = 0; j < 8; j++)
        #pragma unroll
        for (int e = 0; e < 4; e++) o[j][e] = 0.0f;
    float rm0 = -1e30f, rm1 = -1e30f, rl0 = 0.0f, rl1 = 0.0f;

    for (int kb = 0; kb < nkb; kb++) {
        if (kb + 1 < nkb) {
            load_kv(kb + 1);
            CP_COMMIT();
            CP_WAIT1();
        } else {
            CP_WAIT0();
        }
        __syncthreads();
        const uint32_t setb = smb + ((kb & 1) ? KV_SET : 0u);

        // ---- S = Q K^T (Q split, K single) ----
        float sc[16][4];
        #pragma unroll
        for (int j = 0; j < 16; j++)
            #pragma unroll
            for (int e = 0; e < 4; e++) sc[j][e] = 0.0f;

        #pragma unroll
        for (int kc = 0; kc < 4; kc++) {
            #pragma unroll
            for (int g = 0; g < 8; g++) {
                uint32_t ad = setb
                    + (uint32_t)(g * 16 + (lane & 7) + ((lane >> 4) << 3)) * 144
                    + (uint32_t)(kc * 16 + (((lane >> 3) & 1) << 3)) * 2;
                uint32_t kh4[4];
                ldm_x4(kh4, ad);
                mma_f16(sc[2 * g],     qh[kc], &kh4[0]);
                mma_f16(sc[2 * g + 1], qh[kc], &kh4[2]);
                mma_f16(sc[2 * g],     ql[kc], &kh4[0]);
                mma_f16(sc[2 * g + 1], ql[kc], &kh4[2]);
            }
        }

        // ---- causal mask (diagonal 128x128 block) ----
        if (kb == qb) {
            int row0 = qb * 128 + m0 + (lane >> 2);
            int col0 = kb * 128 + (lane & 3) * 2;
            #pragma unroll
            for (int nt = 0; nt < 16; nt++) {
                int cl = col0 + nt * 8;
                if (cl     > row0)     sc[nt][0] = -1e30f;
                if (cl + 1 > row0)     sc[nt][1] = -1e30f;
                if (cl     > row0 + 8) sc[nt][2] = -1e30f;
                if (cl + 1 > row0 + 8) sc[nt][3] = -1e30f;
            }
        }

        // ---- online softmax (base-2) ----
        float mx0 = -1e30f, mx1 = -1e30f;
        #pragma unroll
        for (int nt = 0; nt < 16; nt++) {
            mx0 = fmaxf(mx0, fmaxf(sc[nt][0], sc[nt][1]));
            mx1 = fmaxf(mx1, fmaxf(sc[nt][2], sc[nt][3]));
        }
        mx0 = fmaxf(mx0, __shfl_xor_sync(0xffffffffu, mx0, 1));
        mx0 = fmaxf(mx0, __shfl_xor_sync(0xffffffffu, mx0, 2));
        mx1 = fmaxf(mx1, __shfl_xor_sync(0xffffffffu, mx1, 1));
        mx1 = fmaxf(mx1, __shfl_xor_sync(0xffffffffu, mx1, 2));
        float nm0 = fmaxf(rm0, mx0), nm1 = fmaxf(rm1, mx1);
        float a0 = fexp2(rm0 - nm0), a1 = fexp2(rm1 - nm1);
        rm0 = nm0; rm1 = nm1;
        float ps0 = 0.0f, ps1 = 0.0f;
        #pragma unroll
        for (int nt = 0; nt < 16; nt++) {
            sc[nt][0] = fexp2(sc[nt][0] - rm0); ps0 += sc[nt][0];
            sc[nt][1] = fexp2(sc[nt][1] - rm0); ps0 += sc[nt][1];
            sc[nt][2] = fexp2(sc[nt][2] - rm1); ps1 += sc[nt][2];
            sc[nt][3] = fexp2(sc[nt][3] - rm1); ps1 += sc[nt][3];
        }
        #pragma unroll
        for (int nt = 0; nt < 8; nt++) {
            o[nt][0] *= a0; o[nt][1] *= a0; o[nt][2] *= a1; o[nt][3] *= a1;
        }
        rl0 = rl0 * a0 + ps0;
        rl1 = rl1 * a1 + ps1;

        // ---- O += P V (P split, V single) ----
        #pragma unroll
        for (int s = 0; s < 8; s++) {
            uint32_t ah[4], al[4];
            split2h(sc[2 * s][0],     sc[2 * s][1],     ah[0], al[0]);
            split2h(sc[2 * s][2],     sc[2 * s][3],     ah[1], al[1]);
            split2h(sc[2 * s + 1][0], sc[2 * s + 1][1], ah[2], al[2]);
            split2h(sc[2 * s + 1][2], sc[2 * s + 1][3], ah[3], al[3]);
            #pragma unroll
            for (int g = 0; g < 4; g++) {
                uint32_t ad = setb + KV_T2        // Vh
                    + (uint32_t)(s * 16 + (lane & 7) + (((lane >> 3) & 1) << 3)) * 144
                    + (uint32_t)(g * 16 + ((lane >> 4) << 3)) * 2;
                uint32_t vh4[4];
                ldm_x4_t(vh4, ad);
                mma_f16(o[2 * g],     ah, &vh4[0]);
                mma_f16(o[2 * g + 1], ah, &vh4[2]);
                mma_f16(o[2 * g],     al, &vh4[0]);
                mma_f16(o[2 * g + 1], al, &vh4[2]);
            }
        }
        __syncthreads();
    }

    // ---- finalize, stage O (fp16, unsplit) in set0 region, coalesced writeout ----
    rl0 += __shfl_xor_sync(0xffffffffu, rl0, 1);
    rl0 += __shfl_xor_sync(0xffffffffu, rl0, 2);
    rl1 += __shfl_xor_sync(0xffffffffu, rl1, 1);
    rl1 += __shfl_xor_sync(0xffffffffu, rl1, 2);
    float inv0 = 1.0f / rl0, inv1 = 1.0f / rl1;

    __syncthreads();
    #pragma unroll
    for (int nt = 0; nt < 8; nt++) {
        uint32_t off0 = (uint32_t)(m0 + (lane >> 2)) * 144 + (uint32_t)(nt * 8 + (lane & 3) * 2) * 2;
        uint32_t off1 = off0 + 8 * 144;
        *(uint32_t*)(smp + off0) = pack2h(o[nt][0] * inv0, o[nt][1] * inv0);
        *(uint32_t*)(smp + off1) = pack2h(o[nt][2] * inv1, o[nt][3] * inv1);
    }
    __syncthreads();

    const size_t obase = ((size_t)b * SS + (size_t)qb * 128) * 2048 + (size_t)h * 64;
    #pragma unroll
    for (int i = 0; i < 4; i++) {
        int idx = tid + i * 256;
        int r = idx >> 3, cc = idx & 7;
        uint4 vh = *(uint4*)(smp + r * 144 + cc * 16);
        size_t oa = obase + (size_t)r * 2048 + cc * 8;
        *(uint4*)(oh_g + oa) = vh;
    }
}

// ===================== launch =====================
extern "C" void kernel_launch(void* const* d_in, const int* in_sizes, int n_in,
                              void* d_out, int out_size)
{
    const float* x       = (const float*)d_in[0];
    const float* wq      = (const float*)d_in[1];
    const float* wk      = (const float*)d_in[2];
    const float* wv      = (const float*)d_in[3];
    const float* wo      = (const float*)d_in[4];
    const float* q_scale = (const float*)d_in[5];
    const float* k_scale = (const float*)d_in[6];
    const float* cosp    = (const float*)d_in[7];
    const float* sinp    = (const float*)d_in[8];

    __half *xhi, *wqh, *wkh, *wvh, *woh;
    __half *qh, *ql, *kh, *vh, *ohi;
    cudaGetSymbolAddress((void**)&xhi, g_xhi);
    cudaGetSymbolAddress((void**)&wqh, g_wqh); cudaGetSymbolAddress((void**)&wkh, g_wkh);
    cudaGetSymbolAddress((void**)&wvh, g_wvh); cudaGetSymbolAddress((void**)&woh, g_woh);
    cudaGetSymbolAddress((void**)&qh, g_qh);   cudaGetSymbolAddress((void**)&ql, g_ql);
    cudaGetSymbolAddress((void**)&kh, g_kh);   cudaGetSymbolAddress((void**)&vh, g_vh);
    cudaGetSymbolAddress((void**)&ohi, g_ohi);

    cudaFuncSetAttribute(qkv_gemm, cudaFuncAttributeMaxDynamicSharedMemorySize, SMEM_GEMM);
    cudaFuncSetAttribute(gemm_out, cudaFuncAttributeMaxDynamicSharedMemorySize, SMEM_GEMM);
    cudaFuncSetAttribute(attn_mma, cudaFuncAttributeMaxDynamicSharedMemorySize, SMEM_ATT);

    // ---- fused conversions (one launch) ----
    convert_all<<<18432, 256>>>(x, xhi, wq, wqh, wk, wkh, wv, wvh, wo, woh);

    // ---- fused QKV projection (single-pass fp16) ----
    qkv_gemm<<<dim3(MROWS / BMg, 24), 256, SMEM_GEMM>>>(
        xhi, wqh, wkh, wvh, qh, ql, kh, vh, q_scale, k_scale, cosp, sinp);

    // ---- attention (Q/P split, K/V single fp16, O unsplit) ----
    attn_mma<<<dim3(SS / 128, BB * NH), 256, SMEM_ATT>>>(qh, ql, kh, vh, ohi);

    // ---- output projection (single-pass fp16) ----
    gemm_out<<<dim3(MROWS / BMg, DD / BNg), 256, SMEM_GEMM>>>(
        ohi, woh, (float*)d_out);
}